// round 2
// baseline (speedup 1.0000x reference)
#include <cuda_runtime.h>
#include <math.h>

// Cascaded biquad (highpass 125 Hz -> lowpass 6 kHz, RBJ, Q=1/sqrt(2)) over
// waveform [C=128, T=160000] float32.
//
// Strategy: overlap-and-discard. The slowest pole (highpass) has radius
// ~0.9659, so state influence decays by ~2e-8 over 512 samples. Each thread
// processes one (channel, chunk) pair: it warms up over the preceding 512
// samples from a zero state (reading real input), then emits its CHUNK
// samples. Chunk 0 starts at n=0 with the true zero initial state (exact).
//
// Mapping: blockIdx.x = chunk index, threadIdx.x = channel. Each thread
// streams a contiguous region with float4 loads/stores (chunk boundaries are
// 512-aligned, T % 4 == 0).

#define CHUNK 1024
#define WARM  512

__global__ __launch_bounds__(128, 8)
void cascade_biquad_kernel(
    const float* __restrict__ in, float* __restrict__ out, int T,
    float b0h, float b1h, float b2h, float na1h, float na2h,
    float b0l, float b1l, float b2l, float na1l, float na2l)
{
    const int c = threadIdx.x;                 // channel
    const int k = blockIdx.x;                  // chunk
    const size_t base = (size_t)c * (size_t)T;

    int p = k * CHUNK;                         // first sample this thread owns
    int w = p - WARM; if (w < 0) w = 0;        // warm-up start
    int e = p + CHUNK; if (e > T) e = T;       // end (exclusive)

    const float4* __restrict__ x4 = reinterpret_cast<const float4*>(in + base);
    float4* __restrict__ o4 = reinterpret_cast<float4*>(out + base);

    float x1 = 0.f, x2 = 0.f;   // input history (highpass FIR)
    float y1 = 0.f, y2 = 0.f;   // highpass output history
    float z1 = 0.f, z2 = 0.f;   // lowpass output history

    // One cascaded-biquad step. The a2 term is folded in first and the a1
    // term last so the loop-carried chain (y1->y, z1->z) is a single FMA.
#define STEP(XV, ZOUT) do {                                   \
        float _x = (XV);                                      \
        float _t = fmaf(b1h, x1, fmaf(b0h, _x, b2h * x2));    \
        float _y = fmaf(na1h, y1, fmaf(na2h, y2, _t));        \
        float _u = fmaf(b1l, y1, fmaf(b0l, _y, b2l * y2));    \
        float _z = fmaf(na1l, z1, fmaf(na2l, z2, _u));        \
        x2 = x1; x1 = _x;                                     \
        y2 = y1; y1 = _y;                                     \
        z2 = z1; z1 = _z;                                     \
        ZOUT = _z;                                            \
    } while (0)

    int n4 = w >> 2;
    const int p4 = p >> 2;
    const int e4 = e >> 2;

    float sink = 0.f;
    // Warm-up: run the recurrence, discard outputs.
    #pragma unroll 4
    for (; n4 < p4; ++n4) {
        float4 xv = x4[n4];
        STEP(xv.x, sink); STEP(xv.y, sink); STEP(xv.z, sink); STEP(xv.w, sink);
    }
    // Owned region: run and store.
    #pragma unroll 4
    for (; n4 < e4; ++n4) {
        float4 xv = x4[n4];
        float4 zv;
        STEP(xv.x, zv.x); STEP(xv.y, zv.y); STEP(xv.z, zv.z); STEP(xv.w, zv.w);
        o4[n4] = zv;
    }
    // Keep the warm-up loop's sink live without a store.
    if (sink != sink && e4 > p4) o4[p4].x = sink;   // never true for finite input
#undef STEP
}

// RBJ cookbook biquad coefficients, normalized by a0 in double precision and
// cast to float32 — matches the reference's numpy float64 -> float32 path.
static void rbj_coeffs(double freq, double sr, double q, bool highpass,
                       float* b0, float* b1, float* b2, float* a1, float* a2)
{
    double w0 = 2.0 * M_PI * freq / sr;
    double cw = cos(w0), sw = sin(w0);
    double alpha = sw / (2.0 * q);
    double bb0, bb1, bb2;
    if (highpass) { bb0 = (1.0 + cw) * 0.5; bb1 = -(1.0 + cw); bb2 = (1.0 + cw) * 0.5; }
    else          { bb0 = (1.0 - cw) * 0.5; bb1 =  (1.0 - cw); bb2 = (1.0 - cw) * 0.5; }
    double a0 = 1.0 + alpha;
    double aa1 = -2.0 * cw;
    double aa2 = 1.0 - alpha;
    *b0 = (float)(bb0 / a0);
    *b1 = (float)(bb1 / a0);
    *b2 = (float)(bb2 / a0);
    *a1 = (float)(aa1 / a0);
    *a2 = (float)(aa2 / a0);
}

extern "C" void kernel_launch(void* const* d_in, const int* in_sizes, int n_in,
                              void* d_out, int out_size)
{
    const float* in = (const float*)d_in[0];
    float* out = (float*)d_out;

    const int C = 128;
    const int T = in_sizes[0] / C;             // 160000

    float b0h, b1h, b2h, a1h, a2h;
    float b0l, b1l, b2l, a1l, a2l;
    rbj_coeffs(125.0,  16000.0, 0.7071067811865476, true,  &b0h, &b1h, &b2h, &a1h, &a2h);
    rbj_coeffs(6000.0, 16000.0, 0.7071067811865476, false, &b0l, &b1l, &b2l, &a1l, &a2l);

    int chunks = (T + CHUNK - 1) / CHUNK;      // 157
    cascade_biquad_kernel<<<chunks, C>>>(
        in, out, T,
        b0h, b1h, b2h, -a1h, -a2h,
        b0l, b1l, b2l, -a1l, -a2l);
}

// round 3
// speedup vs baseline: 1.1829x; 1.1829x over previous
#include <cuda_runtime.h>
#include <math.h>

// Cascaded biquad (highpass 125 Hz -> lowpass 6 kHz, RBJ, Q=1/sqrt(2)) over
// waveform [C=128, T=160000] float32.
//
// Overlap-and-discard: slowest pole radius ~0.96593 -> state influence decays
// to ~1.7e-6 over 384 samples. Each thread owns one (channel, chunk) pair,
// warms up from zero state over the preceding WARM samples, then emits CHUNK
// samples. Chunk 0 is exact (true zero initial condition).
//
// R2 changes vs R1 (which was latency-bound: occ 6.7%, issue 11.8%, DRAM 16%):
//  - CHUNK 1024 -> 256: 625 blocks instead of 157 -> ~4 warps/SMSP to hide
//    FMA-chain and DRAM latency.
//  - WARM 512 -> 384: cuts redundant warm-up work 25%.
//  - software prefetch of the next float4 so the load for iteration i+1 is in
//    flight while iteration i computes (breaks LDG->use serialization).

#define CHUNK 256
#define WARM  384

__global__ __launch_bounds__(128)
void cascade_biquad_kernel(
    const float* __restrict__ in, float* __restrict__ out, int T,
    float b0h, float b1h, float b2h, float na1h, float na2h,
    float b0l, float b1l, float b2l, float na1l, float na2l)
{
    const int c = threadIdx.x;                 // channel
    const int k = blockIdx.x;                  // chunk
    const size_t base = (size_t)c * (size_t)T;

    int p = k * CHUNK;                         // first sample this thread owns
    int w = p - WARM; if (w < 0) w = 0;        // warm-up start
    int e = p + CHUNK; if (e > T) e = T;       // end (exclusive)

    const float4* __restrict__ x4 = reinterpret_cast<const float4*>(in + base);
    float4* __restrict__ o4 = reinterpret_cast<float4*>(out + base);

    float x1 = 0.f, x2 = 0.f;   // input history (highpass FIR)
    float y1 = 0.f, y2 = 0.f;   // highpass output history
    float z1 = 0.f, z2 = 0.f;   // lowpass output history

    // One cascaded-biquad step. a2 term folded first, a1 term last, so the
    // loop-carried chains (y1->y, z1->z) are each a single FMA deep.
#define STEP(XV, ZOUT) do {                                   \
        float _x = (XV);                                      \
        float _t = fmaf(b1h, x1, fmaf(b0h, _x, b2h * x2));    \
        float _y = fmaf(na1h, y1, fmaf(na2h, y2, _t));        \
        float _u = fmaf(b1l, y1, fmaf(b0l, _y, b2l * y2));    \
        float _z = fmaf(na1l, z1, fmaf(na2l, z2, _u));        \
        x2 = x1; x1 = _x;                                     \
        y2 = y1; y1 = _y;                                     \
        z2 = z1; z1 = _z;                                     \
        ZOUT = _z;                                            \
    } while (0)

    int n4 = w >> 2;
    const int p4 = p >> 2;
    const int e4 = e >> 2;
    const int T4 = T >> 2;

    float4 xv = x4[n4];        // prime the pipeline
    float dump;

    // Warm-up: run the recurrence, discard outputs. (n4+1 <= p4 < e4 <= T4,
    // so the prefetch below is always in-bounds.)
    #pragma unroll 4
    for (; n4 < p4; ++n4) {
        float4 nx = x4[n4 + 1];
        STEP(xv.x, dump); STEP(xv.y, dump); STEP(xv.z, dump); STEP(xv.w, dump);
        xv = nx;
    }
    // Owned region: run and store. Prefetch clamped at the array end.
    #pragma unroll 4
    for (; n4 < e4; ++n4) {
        int nn = n4 + 1 < T4 ? n4 + 1 : n4;
        float4 nx = x4[nn];
        float4 zv;
        STEP(xv.x, zv.x); STEP(xv.y, zv.y); STEP(xv.z, zv.z); STEP(xv.w, zv.w);
        o4[n4] = zv;
        xv = nx;
    }
#undef STEP
}

// RBJ cookbook biquad coefficients, normalized by a0 in double precision and
// cast to float32 — matches the reference's numpy float64 -> float32 path.
static void rbj_coeffs(double freq, double sr, double q, bool highpass,
                       float* b0, float* b1, float* b2, float* a1, float* a2)
{
    double w0 = 2.0 * M_PI * freq / sr;
    double cw = cos(w0), sw = sin(w0);
    double alpha = sw / (2.0 * q);
    double bb0, bb1, bb2;
    if (highpass) { bb0 = (1.0 + cw) * 0.5; bb1 = -(1.0 + cw); bb2 = (1.0 + cw) * 0.5; }
    else          { bb0 = (1.0 - cw) * 0.5; bb1 =  (1.0 - cw); bb2 = (1.0 - cw) * 0.5; }
    double a0 = 1.0 + alpha;
    double aa1 = -2.0 * cw;
    double aa2 = 1.0 - alpha;
    *b0 = (float)(bb0 / a0);
    *b1 = (float)(bb1 / a0);
    *b2 = (float)(bb2 / a0);
    *a1 = (float)(aa1 / a0);
    *a2 = (float)(aa2 / a0);
}

extern "C" void kernel_launch(void* const* d_in, const int* in_sizes, int n_in,
                              void* d_out, int out_size)
{
    const float* in = (const float*)d_in[0];
    float* out = (float*)d_out;

    const int C = 128;
    const int T = in_sizes[0] / C;             // 160000

    float b0h, b1h, b2h, a1h, a2h;
    float b0l, b1l, b2l, a1l, a2l;
    rbj_coeffs(125.0,  16000.0, 0.7071067811865476, true,  &b0h, &b1h, &b2h, &a1h, &a2h);
    rbj_coeffs(6000.0, 16000.0, 0.7071067811865476, false, &b0l, &b1l, &b2l, &a1l, &a2l);

    int chunks = (T + CHUNK - 1) / CHUNK;      // 625
    cascade_biquad_kernel<<<chunks, C>>>(
        in, out, T,
        b0h, b1h, b2h, -a1h, -a2h,
        b0l, b1l, b2l, -a1l, -a2l);
}